// round 8
// baseline (speedup 1.0000x reference)
#include <cuda_runtime.h>
#include <cstdint>

#define SEQ    2048
#define DM     1024
#define NH     16
#define HD     64
#define BATCH  4
#define BHN    (BATCH * NH)      // 64
#define TOK    (BATCH * SEQ)     // 8192

// Scratch: [B,H,S,hd] layouts, fp32
__device__ float g_Q [(size_t)BHN * SEQ * HD];
__device__ float g_K [(size_t)BHN * SEQ * HD];
__device__ float g_V [(size_t)BHN * SEQ * HD];
__device__ float g_AO[(size_t)BHN * SEQ * HD];

__device__ __forceinline__ uint32_t f2tf32(float x) {
    uint32_t u;
    asm volatile("cvt.rna.tf32.f32 %0, %1;" : "=r"(u) : "f"(x));
    return u;
}

__device__ __forceinline__ void mma_tf32(float c[4], const uint32_t a[4], const uint32_t b[2]) {
    asm volatile(
        "mma.sync.aligned.m16n8k8.row.col.f32.tf32.tf32.f32 "
        "{%0,%1,%2,%3}, {%4,%5,%6,%7}, {%8,%9}, {%0,%1,%2,%3};"
        : "+f"(c[0]), "+f"(c[1]), "+f"(c[2]), "+f"(c[3])
        : "r"(a[0]), "r"(a[1]), "r"(a[2]), "r"(a[3]), "r"(b[0]), "r"(b[1]));
}

__device__ __forceinline__ void cp16(float* dst, const float* src) {
    asm volatile("cp.async.cg.shared.global [%0], [%1], 16;"
                 :: "r"((uint32_t)__cvta_generic_to_shared(dst)), "l"(src));
}
__device__ __forceinline__ void cp_commit() {
    asm volatile("cp.async.commit_group;");
}
template<int N>
__device__ __forceinline__ void cp_wait() {
    asm volatile("cp.async.wait_group %0;" :: "n"(N));
}

// ---------------------------------------------------------------------------
// tf32 tensor-core GEMM (unchanged, proven in R3)
// ---------------------------------------------------------------------------
#define BK   32
#define LDA  36

template<int AMODE, int OMODE>
__global__ __launch_bounds__(256)
void tgemm_kernel(const float* __restrict__ A, const float* __restrict__ W,
                  const float* __restrict__ bias, float* __restrict__ C,
                  int M, int N, int K)
{
    __shared__ float As[128 * LDA];
    __shared__ float Bs[128 * LDA];

    const int tid  = threadIdx.x;
    const int lane = tid & 31;
    const int warp = tid >> 5;
    const int grp  = lane >> 2;
    const int tig  = lane & 3;
    const int wm   = warp & 1;
    const int wn   = warp >> 1;
    const int rowBase = blockIdx.y * 128;
    const int colBase = blockIdx.x * 128;

    const int lrow = tid >> 3;
    const int lk   = (tid & 7) * 4;

    float acc[4][4][4];
#pragma unroll
    for (int i = 0; i < 4; i++)
#pragma unroll
        for (int j = 0; j < 4; j++)
#pragma unroll
            for (int c = 0; c < 4; c++) acc[i][j][c] = 0.f;

    float4 aReg[4], bReg[4];

    auto fetch = [&](int k0) {
#pragma unroll
        for (int p = 0; p < 4; p++) {
            const int r = lrow + p * 32;
            const int kk = k0 + lk;
            const float* ap;
            if (AMODE == 0) {
                ap = A + (size_t)(rowBase + r) * K + kk;
            } else {
                const int m = rowBase + r;
                const int b = m >> 11, s = m & 2047;
                const int h = kk >> 6, d = kk & 63;
                ap = A + (((size_t)(b * NH + h) * SEQ + s) << 6) + d;
            }
            aReg[p] = *(const float4*)ap;
            bReg[p] = *(const float4*)(W + (size_t)(colBase + r) * K + kk);
        }
    };

    auto stage = [&]() {
#pragma unroll
        for (int p = 0; p < 4; p++) {
            const int r = lrow + p * 32;
            uint4 av, bv;
            av.x = f2tf32(aReg[p].x); av.y = f2tf32(aReg[p].y);
            av.z = f2tf32(aReg[p].z); av.w = f2tf32(aReg[p].w);
            bv.x = f2tf32(bReg[p].x); bv.y = f2tf32(bReg[p].y);
            bv.z = f2tf32(bReg[p].z); bv.w = f2tf32(bReg[p].w);
            *(uint4*)&As[r * LDA + lk] = av;
            *(uint4*)&Bs[r * LDA + lk] = bv;
        }
    };

    fetch(0);
    const int ntile = K / BK;
    for (int t = 0; t < ntile; t++) {
        __syncthreads();
        stage();
        __syncthreads();
        if (t + 1 < ntile) fetch((t + 1) * BK);

#pragma unroll
        for (int ks = 0; ks < 4; ks++) {
            const int k = ks * 8;
            uint32_t af[4][4], bf[4][2];
#pragma unroll
            for (int mt = 0; mt < 4; mt++) {
                const int m0 = wm * 64 + mt * 16;
                af[mt][0] = __float_as_uint(As[(m0 + grp)     * LDA + k + tig]);
                af[mt][1] = __float_as_uint(As[(m0 + grp + 8) * LDA + k + tig]);
                af[mt][2] = __float_as_uint(As[(m0 + grp)     * LDA + k + tig + 4]);
                af[mt][3] = __float_as_uint(As[(m0 + grp + 8) * LDA + k + tig + 4]);
            }
#pragma unroll
            for (int nt = 0; nt < 4; nt++) {
                const int n0 = wn * 32 + nt * 8;
                bf[nt][0] = __float_as_uint(Bs[(n0 + grp) * LDA + k + tig]);
                bf[nt][1] = __float_as_uint(Bs[(n0 + grp) * LDA + k + tig + 4]);
            }
#pragma unroll
            for (int mt = 0; mt < 4; mt++)
#pragma unroll
                for (int nt = 0; nt < 4; nt++)
                    mma_tf32(acc[mt][nt], af[mt], bf[nt]);
        }
    }

#pragma unroll
    for (int mt = 0; mt < 4; mt++) {
#pragma unroll
        for (int half = 0; half < 2; half++) {
            const int m = rowBase + wm * 64 + mt * 16 + grp + half * 8;
            const int b = m >> 11, s = m & 2047;
#pragma unroll
            for (int nt = 0; nt < 4; nt++) {
                const int n = colBase + wn * 32 + nt * 8 + 2 * tig;
                float2 r;
                r.x = acc[mt][nt][half * 2 + 0] + bias[n + 0];
                r.y = acc[mt][nt][half * 2 + 1] + bias[n + 1];
                if (OMODE == 0) {
                    *(float2*)(C + (size_t)m * N + n) = r;
                } else {
                    const int h = n >> 6, d = n & 63;
                    *(float2*)(C + (((size_t)(b * NH + h) * SEQ + s) << 6) + d) = r;
                }
            }
        }
    }
}

// ---------------------------------------------------------------------------
// Tensor-core flash attention v3:
//  - BM=64, 128 threads (4 warps x 16 rows), softmax warp-local
//  - cp.async 2-stage double buffer of raw fp32 K/V
//  - NEW: cooperative in-place conversion after each tile lands:
//      K -> tf32 hi (in place) + lo (single Klo buffer); V -> tf32 in place.
//    Inner MMA loops are pure LDS+MMA (no per-warp redundant cvt).
//  - smem 104.4 KB -> 2 CTAs/SM
// ---------------------------------------------------------------------------
#define ALD 68
#define AT_K(buf)  ((buf) * (64 * ALD))                 // Kraw/Khi [2]
#define AT_V(buf)  ((2 + (buf)) * (64 * ALD))           // Vraw/Vtf [2]
#define AT_KLO     (4 * (64 * ALD))                     // K_lo (single)
#define AT_P       (5 * (64 * ALD))                     // P / Q staging
#define ATTN_SMEM_FLOATS (6 * 64 * ALD)
#define ATTN_SMEM_BYTES  (ATTN_SMEM_FLOATS * 4)         // 104448 B

__global__ __launch_bounds__(128)
void attn_tc_kernel(const float* __restrict__ Qg, const float* __restrict__ Kg,
                    const float* __restrict__ Vg, float* __restrict__ Og)
{
    extern __shared__ float smem[];
    float* Klo = smem + AT_KLO;
    float* Ps  = smem + AT_P;

    const int tid  = threadIdx.x;
    const int lane = tid & 31;
    const int warp = tid >> 5;
    const int grp  = lane >> 2;
    const int tig  = lane & 3;
    const int m0   = warp * 16;          // warp's 16 rows
    const int bh   = blockIdx.y;
    const int q0   = blockIdx.x * 64;

    const float* Qb = Qg + ((size_t)bh * SEQ + q0) * HD;
    const float* Kb = Kg + (size_t)bh * SEQ * HD;
    const float* Vb = Vg + (size_t)bh * SEQ * HD;

    // ---- prefetch kv tile 0 ----
    {
        float* Kd = smem + AT_K(0);
        float* Vd = smem + AT_V(0);
        for (int i = tid; i < 64 * 16; i += 128) {
            const int r = i >> 4, c4 = (i & 15) * 4;
            cp16(&Kd[r * ALD + c4], Kb + (size_t)r * HD + c4);
            cp16(&Vd[r * ALD + c4], Vb + (size_t)r * HD + c4);
        }
        cp_commit();
    }

    // ---- stage Q into Ps, build Q fragments (0.125 scale folded) ----
    for (int i = tid; i < 64 * 16; i += 128) {
        const int r = i >> 4, c4 = (i & 15) * 4;
        *(float4*)&Ps[r * ALD + c4] = *(const float4*)(Qb + (size_t)r * HD + c4);
    }
    __syncthreads();

    uint32_t qa[8][4];
#pragma unroll
    for (int ks = 0; ks < 8; ks++) {
        qa[ks][0] = f2tf32(0.125f * Ps[(m0 + grp)     * ALD + ks * 8 + tig]);
        qa[ks][1] = f2tf32(0.125f * Ps[(m0 + grp + 8) * ALD + ks * 8 + tig]);
        qa[ks][2] = f2tf32(0.125f * Ps[(m0 + grp)     * ALD + ks * 8 + tig + 4]);
        qa[ks][3] = f2tf32(0.125f * Ps[(m0 + grp + 8) * ALD + ks * 8 + tig + 4]);
    }
    __syncthreads();   // all warps done reading Q staging before P overwrites

    float o[8][4];
    float mi[2], li[2];
    mi[0] = mi[1] = -1e30f; li[0] = li[1] = 0.f;
#pragma unroll
    for (int nt = 0; nt < 8; nt++)
#pragma unroll
        for (int c = 0; c < 4; c++) o[nt][c] = 0.f;

    const int NT = SEQ / 64;   // 32
    for (int t = 0; t < NT; t++) {
        const int cur = t & 1;
        // prefetch next tile into other raw buffer
        if (t + 1 < NT) {
            float* Kd = smem + AT_K(1 - cur);
            float* Vd = smem + AT_V(1 - cur);
            const size_t off = (size_t)(t + 1) * 64 * HD;
            for (int i = tid; i < 64 * 16; i += 128) {
                const int r = i >> 4, c4 = (i & 15) * 4;
                cp16(&Kd[r * ALD + c4], Kb + off + (size_t)r * HD + c4);
                cp16(&Vd[r * ALD + c4], Vb + off + (size_t)r * HD + c4);
            }
            cp_commit();
            cp_wait<1>();
        } else {
            cp_wait<0>();
        }
        __syncthreads();   // raw tile t visible to all warps

        float* Ks = smem + AT_K(cur);
        float* Vs = smem + AT_V(cur);

        // ---- cooperative in-place conversion ----
        for (int i = tid; i < 64 * 16; i += 128) {
            const int r = i >> 4, c4 = (i & 15) * 4;
            float4 k4 = *(const float4*)&Ks[r * ALD + c4];
            uint4 h, l;
            h.x = f2tf32(k4.x); l.x = f2tf32(k4.x - __uint_as_float(h.x));
            h.y = f2tf32(k4.y); l.y = f2tf32(k4.y - __uint_as_float(h.y));
            h.z = f2tf32(k4.z); l.z = f2tf32(k4.z - __uint_as_float(h.z));
            h.w = f2tf32(k4.w); l.w = f2tf32(k4.w - __uint_as_float(h.w));
            *(uint4*)&Ks[r * ALD + c4]  = h;
            *(uint4*)&Klo[r * ALD + c4] = l;
            float4 v4 = *(const float4*)&Vs[r * ALD + c4];
            uint4 vv;
            vv.x = f2tf32(v4.x); vv.y = f2tf32(v4.y);
            vv.z = f2tf32(v4.z); vv.w = f2tf32(v4.w);
            *(uint4*)&Vs[r * ALD + c4] = vv;
        }
        __syncthreads();

        // ---- S = Q*K_hi^T + Q*K_lo^T : pure LDS + MMA ----
        float s[8][4];
#pragma unroll
        for (int nt = 0; nt < 8; nt++)
#pragma unroll
            for (int c = 0; c < 4; c++) s[nt][c] = 0.f;

#pragma unroll
        for (int ks = 0; ks < 8; ks++) {
#pragma unroll
            for (int nt = 0; nt < 8; nt++) {
                const int n = nt * 8 + grp;
                uint32_t bh2[2], bl2[2];
                bh2[0] = __float_as_uint(Ks [n * ALD + ks * 8 + tig]);
                bh2[1] = __float_as_uint(Ks [n * ALD + ks * 8 + tig + 4]);
                bl2[0] = __float_as_uint(Klo[n * ALD + ks * 8 + tig]);
                bl2[1] = __float_as_uint(Klo[n * ALD + ks * 8 + tig + 4]);
                mma_tf32(s[nt], qa[ks], bh2);
                mma_tf32(s[nt], qa[ks], bl2);
            }
        }

        // ---- online softmax (warp-local rows) ----
        float alpha[2];
#pragma unroll
        for (int h = 0; h < 2; h++) {
            float mx = -1e30f;
#pragma unroll
            for (int nt = 0; nt < 8; nt++)
                mx = fmaxf(mx, fmaxf(s[nt][2 * h], s[nt][2 * h + 1]));
            mx = fmaxf(mx, __shfl_xor_sync(0xffffffffu, mx, 1));
            mx = fmaxf(mx, __shfl_xor_sync(0xffffffffu, mx, 2));
            const float mnew = fmaxf(mi[h], mx);
            alpha[h] = __expf(mi[h] - mnew);
            float rs = 0.f;
#pragma unroll
            for (int nt = 0; nt < 8; nt++) {
                s[nt][2 * h]     = __expf(s[nt][2 * h]     - mnew);
                s[nt][2 * h + 1] = __expf(s[nt][2 * h + 1] - mnew);
                rs += s[nt][2 * h] + s[nt][2 * h + 1];
            }
            rs += __shfl_xor_sync(0xffffffffu, rs, 1);
            rs += __shfl_xor_sync(0xffffffffu, rs, 2);
            li[h] = li[h] * alpha[h] + rs;
            mi[h] = mnew;
        }
#pragma unroll
        for (int nt = 0; nt < 8; nt++)
#pragma unroll
            for (int c = 0; c < 4; c++)
                o[nt][c] *= alpha[c >> 1];

        // ---- store P (plain tf32, warp-private rows) ----
#pragma unroll
        for (int h = 0; h < 2; h++) {
            const int row = m0 + grp + 8 * h;
#pragma unroll
            for (int nt = 0; nt < 8; nt++) {
                uint2 p;
                p.x = f2tf32(s[nt][2 * h]);
                p.y = f2tf32(s[nt][2 * h + 1]);
                *(uint2*)&Ps[row * ALD + nt * 8 + 2 * tig] = p;
            }
        }
        __syncwarp();

        // ---- O += P * V : pure LDS + MMA ----
#pragma unroll
        for (int ks = 0; ks < 8; ks++) {
            uint32_t ah[4];
            ah[0] = __float_as_uint(Ps[(m0 + grp)     * ALD + ks * 8 + tig]);
            ah[1] = __float_as_uint(Ps[(m0 + grp + 8) * ALD + ks * 8 + tig]);
            ah[2] = __float_as_uint(Ps[(m0 + grp)     * ALD + ks * 8 + tig + 4]);
            ah[3] = __float_as_uint(Ps[(m0 + grp + 8) * ALD + ks * 8 + tig + 4]);
#pragma unroll
            for (int nt = 0; nt < 8; nt++) {
                const int d = nt * 8 + grp;
                uint32_t bv2[2];
                bv2[0] = __float_as_uint(Vs[(ks * 8 + tig)     * ALD + d]);
                bv2[1] = __float_as_uint(Vs[(ks * 8 + tig + 4) * ALD + d]);
                mma_tf32(o[nt], ah, bv2);
            }
        }
        __syncthreads();   // all warps done with buf[cur] before it's refilled
    }

    // ---- epilogue ----
    float* Ob = Og + ((size_t)bh * SEQ + q0) * HD;
#pragma unroll
    for (int h = 0; h < 2; h++) {
        const int row = m0 + grp + 8 * h;
        const float inv = 1.0f / li[h];
#pragma unroll
        for (int nt = 0; nt < 8; nt++) {
            const int d = nt * 8 + 2 * tig;
            float2 r;
            r.x = o[nt][2 * h]     * inv;
            r.y = o[nt][2 * h + 1] * inv;
            *(float2*)&Ob[(size_t)row * HD + d] = r;
        }
    }
}

// ---------------------------------------------------------------------------
extern "C" void kernel_launch(void* const* d_in, const int* in_sizes, int n_in,
                              void* d_out, int out_size)
{
    const float* q  = (const float*)d_in[0];
    const float* k  = (const float*)d_in[1];
    const float* v  = (const float*)d_in[2];
    const float* Wq = (const float*)d_in[3];
    const float* bq = (const float*)d_in[4];
    const float* Wk = (const float*)d_in[5];
    const float* bk = (const float*)d_in[6];
    const float* Wv = (const float*)d_in[7];
    const float* bv = (const float*)d_in[8];
    const float* Wo = (const float*)d_in[9];
    const float* bo = (const float*)d_in[10];
    float* out = (float*)d_out;

    float *Qb, *Kb, *Vb, *Ob;
    cudaGetSymbolAddress((void**)&Qb, g_Q);
    cudaGetSymbolAddress((void**)&Kb, g_K);
    cudaGetSymbolAddress((void**)&Vb, g_V);
    cudaGetSymbolAddress((void**)&Ob, g_AO);

    cudaFuncSetAttribute(attn_tc_kernel,
                         cudaFuncAttributeMaxDynamicSharedMemorySize, ATTN_SMEM_BYTES);

    dim3 blk(256);
    dim3 gProj(DM / 128, TOK / 128);   // (8, 64)

    tgemm_kernel<0, 1><<<gProj, blk>>>(q, Wq, bq, Qb, TOK, DM, DM);
    tgemm_kernel<0, 1><<<gProj, blk>>>(k, Wk, bk, Kb, TOK, DM, DM);
    tgemm_kernel<0, 1><<<gProj, blk>>>(v, Wv, bv, Vb, TOK, DM, DM);

    attn_tc_kernel<<<dim3(SEQ / 64, BHN), dim3(128), ATTN_SMEM_BYTES>>>(Qb, Kb, Vb, Ob);

    tgemm_kernel<1, 0><<<gProj, blk>>>(Ob, Wo, bo, out, TOK, DM, DM);
}

// round 9
// speedup vs baseline: 1.2160x; 1.2160x over previous
#include <cuda_runtime.h>
#include <cuda_bf16.h>
#include <cstdint>

#define SEQ    2048
#define DM     1024
#define NH     16
#define HD     64
#define BATCH  4
#define BHN    (BATCH * NH)      // 64
#define TOK    (BATCH * SEQ)     // 8192
#define KVN    ((size_t)BHN * SEQ * HD)   // 8388608 elems per tensor

// fp32 scratch
__device__ float g_Q [KVN];
__device__ float g_K [KVN];
__device__ float g_V [KVN];
__device__ float g_AO[KVN];
// bf16 hi/lo scratch
__device__ __nv_bfloat16 g_Kh [KVN];   // [bh][s][d]
__device__ __nv_bfloat16 g_Kl [KVN];
__device__ __nv_bfloat16 g_Vth[KVN];   // [bh][d][s]
__device__ __nv_bfloat16 g_Vtl[KVN];

__device__ __forceinline__ uint32_t f2tf32(float x) {
    uint32_t u;
    asm volatile("cvt.rna.tf32.f32 %0, %1;" : "=r"(u) : "f"(x));
    return u;
}

__device__ __forceinline__ void mma_tf32(float c[4], const uint32_t a[4], const uint32_t b[2]) {
    asm volatile(
        "mma.sync.aligned.m16n8k8.row.col.f32.tf32.tf32.f32 "
        "{%0,%1,%2,%3}, {%4,%5,%6,%7}, {%8,%9}, {%0,%1,%2,%3};"
        : "+f"(c[0]), "+f"(c[1]), "+f"(c[2]), "+f"(c[3])
        : "r"(a[0]), "r"(a[1]), "r"(a[2]), "r"(a[3]), "r"(b[0]), "r"(b[1]));
}

__device__ __forceinline__ void mma_bf16(float c[4], const uint32_t a[4],
                                         uint32_t b0, uint32_t b1) {
    asm volatile(
        "mma.sync.aligned.m16n8k16.row.col.f32.bf16.bf16.f32 "
        "{%0,%1,%2,%3}, {%4,%5,%6,%7}, {%8,%9}, {%0,%1,%2,%3};"
        : "+f"(c[0]), "+f"(c[1]), "+f"(c[2]), "+f"(c[3])
        : "r"(a[0]), "r"(a[1]), "r"(a[2]), "r"(a[3]), "r"(b0), "r"(b1));
}

// split two floats into packed bf16x2 hi and lo
__device__ __forceinline__ void split2(float x, float y, uint32_t& hi, uint32_t& lo) {
    __nv_bfloat16 hx = __float2bfloat16(x), hy = __float2bfloat16(y);
    __nv_bfloat162 hp = __halves2bfloat162(hx, hy);
    hi = *(uint32_t*)&hp;
    __nv_bfloat16 lx = __float2bfloat16(x - __bfloat162float(hx));
    __nv_bfloat16 ly = __float2bfloat16(y - __bfloat162float(hy));
    __nv_bfloat162 lp = __halves2bfloat162(lx, ly);
    lo = *(uint32_t*)&lp;
}

__device__ __forceinline__ void cp16(void* dst, const void* src) {
    asm volatile("cp.async.cg.shared.global [%0], [%1], 16;"
                 :: "r"((uint32_t)__cvta_generic_to_shared(dst)), "l"(src));
}
__device__ __forceinline__ void cp_commit() {
    asm volatile("cp.async.commit_group;");
}
template<int N>
__device__ __forceinline__ void cp_wait() {
    asm volatile("cp.async.wait_group %0;" :: "n"(N));
}

// ---------------------------------------------------------------------------
// tf32 tensor-core GEMM (unchanged, proven since R3)
// ---------------------------------------------------------------------------
#define BK   32
#define LDA  36

template<int AMODE, int OMODE>
__global__ __launch_bounds__(256)
void tgemm_kernel(const float* __restrict__ A, const float* __restrict__ W,
                  const float* __restrict__ bias, float* __restrict__ C,
                  int M, int N, int K)
{
    __shared__ float As[128 * LDA];
    __shared__ float Bs[128 * LDA];

    const int tid  = threadIdx.x;
    const int lane = tid & 31;
    const int warp = tid >> 5;
    const int grp  = lane >> 2;
    const int tig  = lane & 3;
    const int wm   = warp & 1;
    const int wn   = warp >> 1;
    const int rowBase = blockIdx.y * 128;
    const int colBase = blockIdx.x * 128;

    const int lrow = tid >> 3;
    const int lk   = (tid & 7) * 4;

    float acc[4][4][4];
#pragma unroll
    for (int i = 0; i < 4; i++)
#pragma unroll
        for (int j = 0; j < 4; j++)
#pragma unroll
            for (int c = 0; c < 4; c++) acc[i][j][c] = 0.f;

    float4 aReg[4], bReg[4];

    auto fetch = [&](int k0) {
#pragma unroll
        for (int p = 0; p < 4; p++) {
            const int r = lrow + p * 32;
            const int kk = k0 + lk;
            const float* ap;
            if (AMODE == 0) {
                ap = A + (size_t)(rowBase + r) * K + kk;
            } else {
                const int m = rowBase + r;
                const int b = m >> 11, s = m & 2047;
                const int h = kk >> 6, d = kk & 63;
                ap = A + (((size_t)(b * NH + h) * SEQ + s) << 6) + d;
            }
            aReg[p] = *(const float4*)ap;
            bReg[p] = *(const float4*)(W + (size_t)(colBase + r) * K + kk);
        }
    };

    auto stage = [&]() {
#pragma unroll
        for (int p = 0; p < 4; p++) {
            const int r = lrow + p * 32;
            uint4 av, bv;
            av.x = f2tf32(aReg[p].x); av.y = f2tf32(aReg[p].y);
            av.z = f2tf32(aReg[p].z); av.w = f2tf32(aReg[p].w);
            bv.x = f2tf32(bReg[p].x); bv.y = f2tf32(bReg[p].y);
            bv.z = f2tf32(bReg[p].z); bv.w = f2tf32(bReg[p].w);
            *(uint4*)&As[r * LDA + lk] = av;
            *(uint4*)&Bs[r * LDA + lk] = bv;
        }
    };

    fetch(0);
    const int ntile = K / BK;
    for (int t = 0; t < ntile; t++) {
        __syncthreads();
        stage();
        __syncthreads();
        if (t + 1 < ntile) fetch((t + 1) * BK);

#pragma unroll
        for (int ks = 0; ks < 4; ks++) {
            const int k = ks * 8;
            uint32_t af[4][4], bf[4][2];
#pragma unroll
            for (int mt = 0; mt < 4; mt++) {
                const int m0 = wm * 64 + mt * 16;
                af[mt][0] = __float_as_uint(As[(m0 + grp)     * LDA + k + tig]);
                af[mt][1] = __float_as_uint(As[(m0 + grp + 8) * LDA + k + tig]);
                af[mt][2] = __float_as_uint(As[(m0 + grp)     * LDA + k + tig + 4]);
                af[mt][3] = __float_as_uint(As[(m0 + grp + 8) * LDA + k + tig + 4]);
            }
#pragma unroll
            for (int nt = 0; nt < 4; nt++) {
                const int n0 = wn * 32 + nt * 8;
                bf[nt][0] = __float_as_uint(Bs[(n0 + grp) * LDA + k + tig]);
                bf[nt][1] = __float_as_uint(Bs[(n0 + grp) * LDA + k + tig + 4]);
            }
#pragma unroll
            for (int mt = 0; mt < 4; mt++)
#pragma unroll
                for (int nt = 0; nt < 4; nt++)
                    mma_tf32(acc[mt][nt], af[mt], bf[nt]);
        }
    }

#pragma unroll
    for (int mt = 0; mt < 4; mt++) {
#pragma unroll
        for (int half = 0; half < 2; half++) {
            const int m = rowBase + wm * 64 + mt * 16 + grp + half * 8;
            const int b = m >> 11, s = m & 2047;
#pragma unroll
            for (int nt = 0; nt < 4; nt++) {
                const int n = colBase + wn * 32 + nt * 8 + 2 * tig;
                float2 r;
                r.x = acc[mt][nt][half * 2 + 0] + bias[n + 0];
                r.y = acc[mt][nt][half * 2 + 1] + bias[n + 1];
                if (OMODE == 0) {
                    *(float2*)(C + (size_t)m * N + n) = r;
                } else {
                    const int h = n >> 6, d = n & 63;
                    *(float2*)(C + (((size_t)(b * NH + h) * SEQ + s) << 6) + d) = r;
                }
            }
        }
    }
}

// ---------------------------------------------------------------------------
// Prep kernels: K -> bf16 hi/lo (same layout); V -> transposed bf16 hi/lo
// ---------------------------------------------------------------------------
__global__ __launch_bounds__(256)
void prep_khl_kernel(const float* __restrict__ K,
                     __nv_bfloat16* __restrict__ Kh, __nv_bfloat16* __restrict__ Kl)
{
    size_t i = (size_t)blockIdx.x * 256 + threadIdx.x;
    if (i >= KVN) return;
    const float x = K[i];
    const __nv_bfloat16 h = __float2bfloat16(x);
    Kh[i] = h;
    Kl[i] = __float2bfloat16(x - __bfloat162float(h));
}

__global__ __launch_bounds__(256)
void prep_vt_kernel(const float* __restrict__ V,
                    __nv_bfloat16* __restrict__ Vth, __nv_bfloat16* __restrict__ Vtl)
{
    __shared__ float tile[64][65];
    const int bh = blockIdx.y;
    const int st = blockIdx.x * 64;
    const int tid = threadIdx.x;
    const float* src = V + ((size_t)bh * SEQ + st) * HD;
    for (int i = tid; i < 64 * 64; i += 256) {
        const int s = i >> 6, d = i & 63;
        tile[s][d] = src[(size_t)s * HD + d];
    }
    __syncthreads();
    for (int i = tid; i < 64 * 64; i += 256) {
        const int d = i >> 6, s = i & 63;
        const float x = tile[s][d];
        const __nv_bfloat16 h = __float2bfloat16(x);
        const size_t o = ((size_t)bh * HD + d) * SEQ + st + s;
        Vth[o] = h;
        Vtl[o] = __float2bfloat16(x - __bfloat162float(h));
    }
}

// ---------------------------------------------------------------------------
// bf16 flash attention (double-pseudo-precision, register-resident P):
//  - BM=64, 128 threads (4 warps x 16 rows), softmax warp-local
//  - K hi/lo + V(transposed) hi/lo precomputed bf16, cp.async double-buffered
//  - QK: Qh*Kh + Ql*Kh + Qh*Kl ; PV: Ph*Vh + Pl*Vh + Ph*Vl (mma m16n8k16)
//  - P fragments built in registers from S accumulators (no smem roundtrip)
//  - smem 72 KB -> 3 CTAs/SM
// ---------------------------------------------------------------------------
#define TLD  72                       // bf16 elems per tile row (64 + 8 pad)
#define TBUF (64 * TLD)               // one tile = 4608 bf16
#define ATTN_SMEM_BYTES (8 * TBUF * 2)   // 73728 B

__global__ __launch_bounds__(128, 3)
void attn_bf16_kernel(const float* __restrict__ Qg,
                      const __nv_bfloat16* __restrict__ Khg,
                      const __nv_bfloat16* __restrict__ Klg,
                      const __nv_bfloat16* __restrict__ Vthg,
                      const __nv_bfloat16* __restrict__ Vtlg,
                      float* __restrict__ Og)
{
    extern __shared__ __nv_bfloat16 smem[];

    const int tid  = threadIdx.x;
    const int lane = tid & 31;
    const int warp = tid >> 5;
    const int grp  = lane >> 2;
    const int tig  = lane & 3;
    const int m0   = warp * 16;
    const int bh   = blockIdx.y;
    const int q0   = blockIdx.x * 64;

    const float* Qb = Qg + ((size_t)bh * SEQ + q0) * HD;
    const size_t kbase = (size_t)bh * SEQ * HD;          // [bh][s][d]
    const size_t vbase = (size_t)bh * HD * SEQ;          // [bh][d][s]

    __nv_bfloat16* KhS[2] = { smem + 0 * TBUF, smem + 1 * TBUF };
    __nv_bfloat16* KlS[2] = { smem + 2 * TBUF, smem + 3 * TBUF };
    __nv_bfloat16* VhS[2] = { smem + 4 * TBUF, smem + 5 * TBUF };
    __nv_bfloat16* VlS[2] = { smem + 6 * TBUF, smem + 7 * TBUF };

    auto prefetch = [&](int t, int buf) {
        const size_t ko = kbase + (size_t)t * 64 * HD;
        const size_t vo = vbase + (size_t)t * 64;
        for (int i = tid; i < 512; i += 128) {
            const int r = i >> 3, c = (i & 7) * 8;
            cp16(KhS[buf] + r * TLD + c, Khg  + ko + (size_t)r * HD + c);
            cp16(KlS[buf] + r * TLD + c, Klg  + ko + (size_t)r * HD + c);
            cp16(VhS[buf] + r * TLD + c, Vthg + vo + (size_t)r * SEQ + c);
            cp16(VlS[buf] + r * TLD + c, Vtlg + vo + (size_t)r * SEQ + c);
        }
    };

    prefetch(0, 0);
    cp_commit();

    // ---- Q fragments from global (0.125 scale folded, hi/lo bf16) ----
    uint32_t qh[4][4], ql[4][4];
#pragma unroll
    for (int ks = 0; ks < 4; ks++) {
#pragma unroll
        for (int p = 0; p < 2; p++) {
            const int kcol = 16 * ks + 2 * tig + 8 * p;
            float2 x0 = *(const float2*)(Qb + (size_t)(m0 + grp)     * HD + kcol);
            float2 x1 = *(const float2*)(Qb + (size_t)(m0 + grp + 8) * HD + kcol);
            split2(0.125f * x0.x, 0.125f * x0.y, qh[ks][2 * p],     ql[ks][2 * p]);
            split2(0.125f * x1.x, 0.125f * x1.y, qh[ks][2 * p + 1], ql[ks][2 * p + 1]);
        }
    }

    float o[8][4];
    float mi[2], li[2];
    mi[0] = mi[1] = -1e30f; li[0] = li[1] = 0.f;
#pragma unroll
    for (int nt = 0; nt < 8; nt++)
#pragma unroll
        for (int c = 0; c < 4; c++) o[nt][c] = 0.f;

    const int NT = SEQ / 64;   // 32
    for (int t = 0; t < NT; t++) {
        const int cur = t & 1;
        if (t + 1 < NT) {
            prefetch(t + 1, 1 - cur);
            cp_commit();
            cp_wait<1>();
        } else {
            cp_wait<0>();
        }
        __syncthreads();

        const __nv_bfloat16* Kh = KhS[cur];
        const __nv_bfloat16* Kl = KlS[cur];
        const __nv_bfloat16* Vh = VhS[cur];
        const __nv_bfloat16* Vl = VlS[cur];

        // ---- S = Qh*Kh + Ql*Kh + Qh*Kl ----
        float s[8][4];
#pragma unroll
        for (int nt = 0; nt < 8; nt++)
#pragma unroll
            for (int c = 0; c < 4; c++) s[nt][c] = 0.f;

#pragma unroll
        for (int ks = 0; ks < 4; ks++) {
#pragma unroll
            for (int nt = 0; nt < 8; nt++) {
                const int off = (nt * 8 + grp) * TLD + 16 * ks + 2 * tig;
                const uint32_t bh0 = *(const uint32_t*)(Kh + off);
                const uint32_t bh1 = *(const uint32_t*)(Kh + off + 8);
                const uint32_t bl0 = *(const uint32_t*)(Kl + off);
                const uint32_t bl1 = *(const uint32_t*)(Kl + off + 8);
                mma_bf16(s[nt], qh[ks], bh0, bh1);
                mma_bf16(s[nt], ql[ks], bh0, bh1);
                mma_bf16(s[nt], qh[ks], bl0, bl1);
            }
        }

        // ---- online softmax (warp-local rows grp, grp+8) ----
        float alpha[2];
#pragma unroll
        for (int h = 0; h < 2; h++) {
            float mx = -1e30f;
#pragma unroll
            for (int nt = 0; nt < 8; nt++)
                mx = fmaxf(mx, fmaxf(s[nt][2 * h], s[nt][2 * h + 1]));
            mx = fmaxf(mx, __shfl_xor_sync(0xffffffffu, mx, 1));
            mx = fmaxf(mx, __shfl_xor_sync(0xffffffffu, mx, 2));
            const float mnew = fmaxf(mi[h], mx);
            alpha[h] = __expf(mi[h] - mnew);
            float rs = 0.f;
#pragma unroll
            for (int nt = 0; nt < 8; nt++) {
                s[nt][2 * h]     = __expf(s[nt][2 * h]     - mnew);
                s[nt][2 * h + 1] = __expf(s[nt][2 * h + 1] - mnew);
                rs += s[nt][2 * h] + s[nt][2 * h + 1];
            }
            rs += __shfl_xor_sync(0xffffffffu, rs, 1);
            rs += __shfl_xor_sync(0xffffffffu, rs, 2);
            li[h] = li[h] * alpha[h] + rs;
            mi[h] = mnew;
        }
#pragma unroll
        for (int nt = 0; nt < 8; nt++)
#pragma unroll
            for (int c = 0; c < 4; c++)
                o[nt][c] *= alpha[c >> 1];

        // ---- O += Ph*Vh + Pl*Vh + Ph*Vl  (P frags built in registers) ----
#pragma unroll
        for (int j = 0; j < 4; j++) {
            uint32_t ah[4], al[4];
            split2(s[2 * j][0],     s[2 * j][1],     ah[0], al[0]);
            split2(s[2 * j][2],     s[2 * j][3],     ah[1], al[1]);
            split2(s[2 * j + 1][0], s[2 * j + 1][1], ah[2], al[2]);
            split2(s[2 * j + 1][2], s[2 * j + 1][3], ah[3], al[3]);
#pragma unroll
            for (int nt = 0; nt < 8; nt++) {
                const int off = (nt * 8 + grp) * TLD + 16 * j + 2 * tig;
                const uint32_t vh0 = *(const uint32_t*)(Vh + off);
                const uint32_t vh1 = *(const uint32_t*)(Vh + off + 8);
                const uint32_t vl0 = *(const uint32_t*)(Vl + off);
                const uint32_t vl1 = *(const uint32_t*)(Vl + off + 8);
                mma_bf16(o[nt], ah, vh0, vh1);
                mma_bf16(o[nt], al, vh0, vh1);
                mma_bf16(o[nt], ah, vl0, vl1);
            }
        }
        __syncthreads();   // all warps done with buf[cur] before it's refilled
    }

    // ---- epilogue ----
    float* Ob = Og + ((size_t)bh * SEQ + q0) * HD;
#pragma unroll
    for (int h = 0; h < 2; h++) {
        const int row = m0 + grp + 8 * h;
        const float inv = 1.0f / li[h];
#pragma unroll
        for (int nt = 0; nt < 8; nt++) {
            const int d = nt * 8 + 2 * tig;
            float2 r;
            r.x = o[nt][2 * h]     * inv;
            r.y = o[nt][2 * h + 1] * inv;
            *(float2*)&Ob[(size_t)row * HD + d] = r;
        }
    }
}

// ---------------------------------------------------------------------------
extern "C" void kernel_launch(void* const* d_in, const int* in_sizes, int n_in,
                              void* d_out, int out_size)
{
    const float* q  = (const float*)d_in[0];
    const float* k  = (const float*)d_in[1];
    const float* v  = (const float*)d_in[2];
    const float* Wq = (const float*)d_in[3];
    const float* bq = (const float*)d_in[4];
    const float* Wk = (const float*)d_in[5];
    const float* bk = (const float*)d_in[6];
    const float* Wv = (const float*)d_in[7];
    const float* bv = (const float*)d_in[8];
    const float* Wo = (const float*)d_in[9];
    const float* bo = (const float*)d_in[10];
    float* out = (float*)d_out;

    float *Qb, *Kb, *Vb, *Ob;
    __nv_bfloat16 *Kh, *Kl, *Vth, *Vtl;
    cudaGetSymbolAddress((void**)&Qb, g_Q);
    cudaGetSymbolAddress((void**)&Kb, g_K);
    cudaGetSymbolAddress((void**)&Vb, g_V);
    cudaGetSymbolAddress((void**)&Ob, g_AO);
    cudaGetSymbolAddress((void**)&Kh, g_Kh);
    cudaGetSymbolAddress((void**)&Kl, g_Kl);
    cudaGetSymbolAddress((void**)&Vth, g_Vth);
    cudaGetSymbolAddress((void**)&Vtl, g_Vtl);

    cudaFuncSetAttribute(attn_bf16_kernel,
                         cudaFuncAttributeMaxDynamicSharedMemorySize, ATTN_SMEM_BYTES);

    dim3 blk(256);
    dim3 gProj(DM / 128, TOK / 128);   // (8, 64)

    tgemm_kernel<0, 1><<<gProj, blk>>>(q, Wq, bq, Qb, TOK, DM, DM);
    tgemm_kernel<0, 1><<<gProj, blk>>>(k, Wk, bk, Kb, TOK, DM, DM);
    tgemm_kernel<0, 1><<<gProj, blk>>>(v, Wv, bv, Vb, TOK, DM, DM);

    prep_khl_kernel<<<(int)((KVN + 255) / 256), 256>>>(Kb, Kh, Kl);
    prep_vt_kernel<<<dim3(SEQ / 64, BHN), 256>>>(Vb, Vth, Vtl);

    attn_bf16_kernel<<<dim3(SEQ / 64, BHN), dim3(128), ATTN_SMEM_BYTES>>>(
        Qb, Kh, Kl, Vth, Vtl, Ob);

    tgemm_kernel<1, 0><<<gProj, blk>>>(Ob, Wo, bo, out, TOK, DM, DM);
}

// round 10
// speedup vs baseline: 1.4094x; 1.1591x over previous
#include <cuda_runtime.h>
#include <cuda_bf16.h>
#include <cstdint>

#define SEQ    2048
#define DM     1024
#define NH     16
#define HD     64
#define BATCH  4
#define BHN    (BATCH * NH)      // 64
#define TOK    (BATCH * SEQ)     // 8192
#define KVN    ((size_t)BHN * SEQ * HD)

// fp32 scratch
__device__ float g_Q [KVN];
__device__ float g_AO[KVN];
// bf16 hi/lo scratch (written directly by projection epilogues)
__device__ __nv_bfloat16 g_Kh [KVN];   // [bh][s][d]
__device__ __nv_bfloat16 g_Kl [KVN];
__device__ __nv_bfloat16 g_Vth[KVN];   // [bh][d][s]
__device__ __nv_bfloat16 g_Vtl[KVN];

__device__ __forceinline__ uint32_t f2tf32(float x) {
    uint32_t u;
    asm volatile("cvt.rna.tf32.f32 %0, %1;" : "=r"(u) : "f"(x));
    return u;
}

__device__ __forceinline__ void mma_tf32(float c[4], const uint32_t a[4], const uint32_t b[2]) {
    asm volatile(
        "mma.sync.aligned.m16n8k8.row.col.f32.tf32.tf32.f32 "
        "{%0,%1,%2,%3}, {%4,%5,%6,%7}, {%8,%9}, {%0,%1,%2,%3};"
        : "+f"(c[0]), "+f"(c[1]), "+f"(c[2]), "+f"(c[3])
        : "r"(a[0]), "r"(a[1]), "r"(a[2]), "r"(a[3]), "r"(b[0]), "r"(b[1]));
}

__device__ __forceinline__ void mma_bf16(float c[4], const uint32_t a[4],
                                         uint32_t b0, uint32_t b1) {
    asm volatile(
        "mma.sync.aligned.m16n8k16.row.col.f32.bf16.bf16.f32 "
        "{%0,%1,%2,%3}, {%4,%5,%6,%7}, {%8,%9}, {%0,%1,%2,%3};"
        : "+f"(c[0]), "+f"(c[1]), "+f"(c[2]), "+f"(c[3])
        : "r"(a[0]), "r"(a[1]), "r"(a[2]), "r"(a[3]), "r"(b0), "r"(b1));
}

__device__ __forceinline__ void ldsm4(uint32_t r[4], uint32_t saddr) {
    asm volatile("ldmatrix.sync.aligned.m8n8.x4.shared.b16 {%0,%1,%2,%3}, [%4];"
                 : "=r"(r[0]), "=r"(r[1]), "=r"(r[2]), "=r"(r[3]) : "r"(saddr));
}

// split two floats into packed bf16x2 hi and lo
__device__ __forceinline__ void split2(float x, float y, uint32_t& hi, uint32_t& lo) {
    __nv_bfloat16 hx = __float2bfloat16(x), hy = __float2bfloat16(y);
    __nv_bfloat162 hp = __halves2bfloat162(hx, hy);
    hi = *(uint32_t*)&hp;
    __nv_bfloat16 lx = __float2bfloat16(x - __bfloat162float(hx));
    __nv_bfloat16 ly = __float2bfloat16(y - __bfloat162float(hy));
    __nv_bfloat162 lp = __halves2bfloat162(lx, ly);
    lo = *(uint32_t*)&lp;
}

__device__ __forceinline__ void splitbf(float x, __nv_bfloat16& h, __nv_bfloat16& l) {
    h = __float2bfloat16(x);
    l = __float2bfloat16(x - __bfloat162float(h));
}

__device__ __forceinline__ void cp16(void* dst, const void* src) {
    asm volatile("cp.async.cg.shared.global [%0], [%1], 16;"
                 :: "r"((uint32_t)__cvta_generic_to_shared(dst)), "l"(src));
}
__device__ __forceinline__ void cp_commit() {
    asm volatile("cp.async.commit_group;");
}
template<int N>
__device__ __forceinline__ void cp_wait() {
    asm volatile("cp.async.wait_group %0;" :: "n"(N));
}

// ---------------------------------------------------------------------------
// tf32 tensor-core GEMM.
// AMODE 0: A row-major.  AMODE 1: A gathered from [B,H,S,hd].
// OMODE 0: C row-major fp32.      OMODE 1: C scattered fp32 [B,H,S,hd].
// OMODE 2: bf16 hi/lo to Ch/Cl in [bh][s][d]   (K projection).
// OMODE 3: bf16 hi/lo to Ch/Cl in [bh][d][s]   (V projection, transposed).
// ---------------------------------------------------------------------------
#define BK   32
#define LDA  36

template<int AMODE, int OMODE>
__global__ __launch_bounds__(256)
void tgemm_kernel(const float* __restrict__ A, const float* __restrict__ W,
                  const float* __restrict__ bias, float* __restrict__ C,
                  __nv_bfloat16* __restrict__ Ch, __nv_bfloat16* __restrict__ Cl,
                  int M, int N, int K)
{
    __shared__ float As[128 * LDA];
    __shared__ float Bs[128 * LDA];

    const int tid  = threadIdx.x;
    const int lane = tid & 31;
    const int warp = tid >> 5;
    const int grp  = lane >> 2;
    const int tig  = lane & 3;
    const int wm   = warp & 1;
    const int wn   = warp >> 1;
    const int rowBase = blockIdx.y * 128;
    const int colBase = blockIdx.x * 128;

    const int lrow = tid >> 3;
    const int lk   = (tid & 7) * 4;

    float acc[4][4][4];
#pragma unroll
    for (int i = 0; i < 4; i++)
#pragma unroll
        for (int j = 0; j < 4; j++)
#pragma unroll
            for (int c = 0; c < 4; c++) acc[i][j][c] = 0.f;

    float4 aReg[4], bReg[4];

    auto fetch = [&](int k0) {
#pragma unroll
        for (int p = 0; p < 4; p++) {
            const int r = lrow + p * 32;
            const int kk = k0 + lk;
            const float* ap;
            if (AMODE == 0) {
                ap = A + (size_t)(rowBase + r) * K + kk;
            } else {
                const int m = rowBase + r;
                const int b = m >> 11, s = m & 2047;
                const int h = kk >> 6, d = kk & 63;
                ap = A + (((size_t)(b * NH + h) * SEQ + s) << 6) + d;
            }
            aReg[p] = *(const float4*)ap;
            bReg[p] = *(const float4*)(W + (size_t)(colBase + r) * K + kk);
        }
    };

    auto stage = [&]() {
#pragma unroll
        for (int p = 0; p < 4; p++) {
            const int r = lrow + p * 32;
            uint4 av, bv;
            av.x = f2tf32(aReg[p].x); av.y = f2tf32(aReg[p].y);
            av.z = f2tf32(aReg[p].z); av.w = f2tf32(aReg[p].w);
            bv.x = f2tf32(bReg[p].x); bv.y = f2tf32(bReg[p].y);
            bv.z = f2tf32(bReg[p].z); bv.w = f2tf32(bReg[p].w);
            *(uint4*)&As[r * LDA + lk] = av;
            *(uint4*)&Bs[r * LDA + lk] = bv;
        }
    };

    fetch(0);
    const int ntile = K / BK;
    for (int t = 0; t < ntile; t++) {
        __syncthreads();
        stage();
        __syncthreads();
        if (t + 1 < ntile) fetch((t + 1) * BK);

#pragma unroll
        for (int ks = 0; ks < 4; ks++) {
            const int k = ks * 8;
            uint32_t af[4][4], bf[4][2];
#pragma unroll
            for (int mt = 0; mt < 4; mt++) {
                const int m0 = wm * 64 + mt * 16;
                af[mt][0] = __float_as_uint(As[(m0 + grp)     * LDA + k + tig]);
                af[mt][1] = __float_as_uint(As[(m0 + grp + 8) * LDA + k + tig]);
                af[mt][2] = __float_as_uint(As[(m0 + grp)     * LDA + k + tig + 4]);
                af[mt][3] = __float_as_uint(As[(m0 + grp + 8) * LDA + k + tig + 4]);
            }
#pragma unroll
            for (int nt = 0; nt < 4; nt++) {
                const int n0 = wn * 32 + nt * 8;
                bf[nt][0] = __float_as_uint(Bs[(n0 + grp) * LDA + k + tig]);
                bf[nt][1] = __float_as_uint(Bs[(n0 + grp) * LDA + k + tig + 4]);
            }
#pragma unroll
            for (int mt = 0; mt < 4; mt++)
#pragma unroll
                for (int nt = 0; nt < 4; nt++)
                    mma_tf32(acc[mt][nt], af[mt], bf[nt]);
        }
    }

#pragma unroll
    for (int mt = 0; mt < 4; mt++) {
#pragma unroll
        for (int half = 0; half < 2; half++) {
            const int m = rowBase + wm * 64 + mt * 16 + grp + half * 8;
            const int b = m >> 11, s = m & 2047;
#pragma unroll
            for (int nt = 0; nt < 4; nt++) {
                const int n = colBase + wn * 32 + nt * 8 + 2 * tig;
                float2 r;
                r.x = acc[mt][nt][half * 2 + 0] + bias[n + 0];
                r.y = acc[mt][nt][half * 2 + 1] + bias[n + 1];
                const int h = n >> 6, d = n & 63;
                if (OMODE == 0) {
                    *(float2*)(C + (size_t)m * N + n) = r;
                } else if (OMODE == 1) {
                    *(float2*)(C + (((size_t)(b * NH + h) * SEQ + s) << 6) + d) = r;
                } else if (OMODE == 2) {
                    const size_t o = (((size_t)(b * NH + h) * SEQ + s) << 6) + d;
                    __nv_bfloat16 hx, lx, hy, ly;
                    splitbf(r.x, hx, lx); splitbf(r.y, hy, ly);
                    __nv_bfloat162 hp = __halves2bfloat162(hx, hy);
                    __nv_bfloat162 lp = __halves2bfloat162(lx, ly);
                    *(__nv_bfloat162*)&Ch[o] = hp;
                    *(__nv_bfloat162*)&Cl[o] = lp;
                } else {
                    const size_t o = ((size_t)(b * NH + h) * HD + d) * SEQ + s;
                    __nv_bfloat16 hx, lx, hy, ly;
                    splitbf(r.x, hx, lx); splitbf(r.y, hy, ly);
                    Ch[o] = hx;       Cl[o] = lx;
                    Ch[o + SEQ] = hy; Cl[o + SEQ] = ly;
                }
            }
        }
    }
}

// ---------------------------------------------------------------------------
// bf16 flash attention (double-pseudo-precision, register P, ldmatrix frags)
//  - BM=64, 128 threads (4 warps x 16 rows), softmax warp-local
//  - K hi/lo + V(transposed) hi/lo bf16 from gmem, cp.async double-buffered
//  - QK: Qh*Kh + Ql*Kh + Qh*Kl ; PV: Ph*Vh + Pl*Vh + Ph*Vl (mma m16n8k16)
//  - All B fragments via ldmatrix.m8n8.x4 (16 scalar LDS -> 1 LDSM)
// ---------------------------------------------------------------------------
#define TLD   72                      // bf16 elems per tile row (64 + 8 pad)
#define TBUF  (64 * TLD)              // one tile = 4608 bf16
#define TBUF2 (TBUF * 2)              // bytes
#define ATTN_SMEM_BYTES (8 * TBUF2)   // 73728 B

__global__ __launch_bounds__(128, 3)
void attn_bf16_kernel(const float* __restrict__ Qg,
                      const __nv_bfloat16* __restrict__ Khg,
                      const __nv_bfloat16* __restrict__ Klg,
                      const __nv_bfloat16* __restrict__ Vthg,
                      const __nv_bfloat16* __restrict__ Vtlg,
                      float* __restrict__ Og)
{
    extern __shared__ __nv_bfloat16 smem[];

    const int tid  = threadIdx.x;
    const int lane = tid & 31;
    const int warp = tid >> 5;
    const int grp  = lane >> 2;
    const int tig  = lane & 3;
    const int m0   = warp * 16;
    const int bh   = blockIdx.y;
    const int q0   = blockIdx.x * 64;

    const float* Qb = Qg + ((size_t)bh * SEQ + q0) * HD;
    const size_t kbase = (size_t)bh * SEQ * HD;          // [bh][s][d]
    const size_t vbase = (size_t)bh * HD * SEQ;          // [bh][d][s]

    __nv_bfloat16* KhS[2] = { smem + 0 * TBUF, smem + 1 * TBUF };
    __nv_bfloat16* KlS[2] = { smem + 2 * TBUF, smem + 3 * TBUF };
    __nv_bfloat16* VhS[2] = { smem + 4 * TBUF, smem + 5 * TBUF };
    __nv_bfloat16* VlS[2] = { smem + 6 * TBUF, smem + 7 * TBUF };

    const uint32_t sb = (uint32_t)__cvta_generic_to_shared(smem);

    // ldmatrix lane-row byte offsets: matrix mi = lane>>3, row mr = lane&7
    // matrix pair layout: {nt=2*npb, k-low}, {2*npb, k-high}, {2*npb+1, low}, {2*npb+1, high}
    const int mi = lane >> 3, mr = lane & 7;
    uint32_t lrow[4];
#pragma unroll
    for (int npb = 0; npb < 4; npb++)
        lrow[npb] = (uint32_t)(((npb * 16 + (mi >> 1) * 8 + mr) * TLD) * 2 + (mi & 1) * 16);

    auto prefetch = [&](int t, int buf) {
        const size_t ko = kbase + (size_t)t * 64 * HD;
        const size_t vo = vbase + (size_t)t * 64;
        for (int i = tid; i < 512; i += 128) {
            const int r = i >> 3, c = (i & 7) * 8;
            cp16(KhS[buf] + r * TLD + c, Khg  + ko + (size_t)r * HD + c);
            cp16(KlS[buf] + r * TLD + c, Klg  + ko + (size_t)r * HD + c);
            cp16(VhS[buf] + r * TLD + c, Vthg + vo + (size_t)r * SEQ + c);
            cp16(VlS[buf] + r * TLD + c, Vtlg + vo + (size_t)r * SEQ + c);
        }
    };

    prefetch(0, 0);
    cp_commit();

    // ---- Q fragments from global (0.125 scale folded, hi/lo bf16) ----
    uint32_t qh[4][4], ql[4][4];
#pragma unroll
    for (int ks = 0; ks < 4; ks++) {
#pragma unroll
        for (int p = 0; p < 2; p++) {
            const int kcol = 16 * ks + 2 * tig + 8 * p;
            float2 x0 = *(const float2*)(Qb + (size_t)(m0 + grp)     * HD + kcol);
            float2 x1 = *(const float2*)(Qb + (size_t)(m0 + grp + 8) * HD + kcol);
            split2(0.125f * x0.x, 0.125f * x0.y, qh[ks][2 * p],     ql[ks][2 * p]);
            split2(0.125f * x1.x, 0.125f * x1.y, qh[ks][2 * p + 1], ql[ks][2 * p + 1]);
        }
    }

    float o[8][4];
    float mi2[2], li[2];
    mi2[0] = mi2[1] = -1e30f; li[0] = li[1] = 0.f;
#pragma unroll
    for (int nt = 0; nt < 8; nt++)
#pragma unroll
        for (int c = 0; c < 4; c++) o[nt][c] = 0.f;

    const int NT = SEQ / 64;   // 32
    for (int t = 0; t < NT; t++) {
        const int cur = t & 1;
        if (t + 1 < NT) {
            prefetch(t + 1, 1 - cur);
            cp_commit();
            cp_wait<1>();
        } else {
            cp_wait<0>();
        }
        __syncthreads();

        const uint32_t khA = sb + (0 + cur) * TBUF2;
        const uint32_t klA = sb + (2 + cur) * TBUF2;
        const uint32_t vhA = sb + (4 + cur) * TBUF2;
        const uint32_t vlA = sb + (6 + cur) * TBUF2;

        // ---- S = Qh*Kh + Ql*Kh + Qh*Kl ----
        float s[8][4];
#pragma unroll
        for (int nt = 0; nt < 8; nt++)
#pragma unroll
            for (int c = 0; c < 4; c++) s[nt][c] = 0.f;

#pragma unroll
        for (int ks = 0; ks < 4; ks++) {
#pragma unroll
            for (int npb = 0; npb < 4; npb++) {
                const uint32_t off = lrow[npb] + ks * 32;
                uint32_t bhf[4], blf[4];
                ldsm4(bhf, khA + off);
                ldsm4(blf, klA + off);
                mma_bf16(s[2 * npb],     qh[ks], bhf[0], bhf[1]);
                mma_bf16(s[2 * npb],     ql[ks], bhf[0], bhf[1]);
                mma_bf16(s[2 * npb],     qh[ks], blf[0], blf[1]);
                mma_bf16(s[2 * npb + 1], qh[ks], bhf[2], bhf[3]);
                mma_bf16(s[2 * npb + 1], ql[ks], bhf[2], bhf[3]);
                mma_bf16(s[2 * npb + 1], qh[ks], blf[2], blf[3]);
            }
        }

        // ---- online softmax (warp-local rows grp, grp+8) ----
        float alpha[2];
#pragma unroll
        for (int h = 0; h < 2; h++) {
            float mx = -1e30f;
#pragma unroll
            for (int nt = 0; nt < 8; nt++)
                mx = fmaxf(mx, fmaxf(s[nt][2 * h], s[nt][2 * h + 1]));
            mx = fmaxf(mx, __shfl_xor_sync(0xffffffffu, mx, 1));
            mx = fmaxf(mx, __shfl_xor_sync(0xffffffffu, mx, 2));
            const float mnew = fmaxf(mi2[h], mx);
            alpha[h] = __expf(mi2[h] - mnew);
            float rs = 0.f;
#pragma unroll
            for (int nt = 0; nt < 8; nt++) {
                s[nt][2 * h]     = __expf(s[nt][2 * h]     - mnew);
                s[nt][2 * h + 1] = __expf(s[nt][2 * h + 1] - mnew);
                rs += s[nt][2 * h] + s[nt][2 * h + 1];
            }
            rs += __shfl_xor_sync(0xffffffffu, rs, 1);
            rs += __shfl_xor_sync(0xffffffffu, rs, 2);
            li[h] = li[h] * alpha[h] + rs;
            mi2[h] = mnew;
        }
#pragma unroll
        for (int nt = 0; nt < 8; nt++)
#pragma unroll
            for (int c = 0; c < 4; c++)
                o[nt][c] *= alpha[c >> 1];

        // ---- O += Ph*Vh + Pl*Vh + Ph*Vl  (P frags in registers) ----
#pragma unroll
        for (int j = 0; j < 4; j++) {
            uint32_t ah[4], al[4];
            split2(s[2 * j][0],     s[2 * j][1],     ah[0], al[0]);
            split2(s[2 * j][2],     s[2 * j][3],     ah[1], al[1]);
            split2(s[2 * j + 1][0], s[2 * j + 1][1], ah[2], al[2]);
            split2(s[2 * j + 1][2], s[2 * j + 1][3], ah[3], al[3]);
#pragma unroll
            for (int npb = 0; npb < 4; npb++) {
                const uint32_t off = lrow[npb] + j * 32;
                uint32_t vhf[4], vlf[4];
                ldsm4(vhf, vhA + off);
                ldsm4(vlf, vlA + off);
                mma_bf16(o[2 * npb],     ah, vhf[0], vhf[1]);
                mma_bf16(o[2 * npb],     al, vhf[0], vhf[1]);
                mma_bf16(o[2 * npb],     ah, vlf[0], vlf[1]);
                mma_bf16(o[2 * npb + 1], ah, vhf[2], vhf[3]);
                mma_bf16(o[2 * npb + 1], al, vhf[2], vhf[3]);
                mma_bf16(o[2 * npb + 1], ah, vlf[2], vlf[3]);
            }
        }
        __syncthreads();   // all warps done with buf[cur] before refill
    }

    // ---- epilogue ----
    float* Ob = Og + ((size_t)bh * SEQ + q0) * HD;
#pragma unroll
    for (int h = 0; h < 2; h++) {
        const int row = m0 + grp + 8 * h;
        const float inv = 1.0f / li[h];
#pragma unroll
        for (int nt = 0; nt < 8; nt++) {
            const int d = nt * 8 + 2 * tig;
            float2 r;
            r.x = o[nt][2 * h]     * inv;
            r.y = o[nt][2 * h + 1] * inv;
            *(float2*)&Ob[(size_t)row * HD + d] = r;
        }
    }
}

// ---------------------------------------------------------------------------
extern "C" void kernel_launch(void* const* d_in, const int* in_sizes, int n_in,
                              void* d_out, int out_size)
{
    const float* q  = (const float*)d_in[0];
    const float* k  = (const float*)d_in[1];
    const float* v  = (const float*)d_in[2];
    const float* Wq = (const float*)d_in[3];
    const float* bq = (const float*)d_in[4];
    const float* Wk = (const float*)d_in[5];
    const float* bk = (const float*)d_in[6];
    const float* Wv = (const float*)d_in[7];
    const float* bv = (const float*)d_in[8];
    const float* Wo = (const float*)d_in[9];
    const float* bo = (const float*)d_in[10];
    float* out = (float*)d_out;

    float *Qb, *Ob;
    __nv_bfloat16 *Kh, *Kl, *Vth, *Vtl;
    cudaGetSymbolAddress((void**)&Qb, g_Q);
    cudaGetSymbolAddress((void**)&Ob, g_AO);
    cudaGetSymbolAddress((void**)&Kh, g_Kh);
    cudaGetSymbolAddress((void**)&Kl, g_Kl);
    cudaGetSymbolAddress((void**)&Vth, g_Vth);
    cudaGetSymbolAddress((void**)&Vtl, g_Vtl);

    cudaFuncSetAttribute(attn_bf16_kernel,
                         cudaFuncAttributeMaxDynamicSharedMemorySize, ATTN_SMEM_BYTES);

    dim3 blk(256);
    dim3 gProj(DM / 128, TOK / 128);   // (8, 64)

    tgemm_kernel<0, 1><<<gProj, blk>>>(q, Wq, bq, Qb, nullptr, nullptr, TOK, DM, DM);
    tgemm_kernel<0, 2><<<gProj, blk>>>(k, Wk, bk, nullptr, Kh, Kl, TOK, DM, DM);
    tgemm_kernel<0, 3><<<gProj, blk>>>(v, Wv, bv, nullptr, Vth, Vtl, TOK, DM, DM);

    attn_bf16_kernel<<<dim3(SEQ / 64, BHN), dim3(128), ATTN_SMEM_BYTES>>>(
        Qb, Kh, Kl, Vth, Vtl, Ob);

    tgemm_kernel<1, 0><<<gProj, blk>>>(Ob, Wo, bo, out, nullptr, nullptr, TOK, DM, DM);
}